// round 9
// baseline (speedup 1.0000x reference)
#include <cuda_runtime.h>
#include <math.h>

#define KNUM 512
#define NPAIR 256      // KNUM/2
#define DDIM 64
#define NROWS 65536    // 16*64*64
#define HW 4096        // 64*64
#define NB 16
#define THREADS 448
#define GP 8           // code-pairs interleaved per thread (independent FFMA2 chains)

typedef unsigned long long ull;

__device__ double g_loss_sum;
__device__ unsigned int g_counts[KNUM];

__device__ __forceinline__ ull ffma2(ull a, ull b, ull c) {
    ull d;
    asm("fma.rn.f32x2 %0, %1, %2, %3;" : "=l"(d) : "l"(a), "l"(b), "l"(c));
    return d;
}
__device__ __forceinline__ ull fadd2(ull a, ull b) {
    ull d;
    asm("add.rn.f32x2 %0, %1, %2;" : "=l"(d) : "l"(a), "l"(b));
    return d;
}
__device__ __forceinline__ ull pack2(float lo, float hi) {
    ull d;
    asm("mov.b64 %0, {%1, %2};" : "=l"(d) : "f"(lo), "f"(hi));
    return d;
}
__device__ __forceinline__ void unpack2(ull v, float& lo, float& hi) {
    asm("mov.b64 {%0, %1}, %2;" : "=f"(lo), "=f"(hi) : "l"(v));
}

__global__ void vq_init_kernel() {
    int t = threadIdx.x;
    if (t < KNUM) g_counts[t] = 0u;
    if (t == 0) g_loss_sum = 0.0;
}

// Shared layout:
//   [0 .. NPAIR*DDIM)        float2  sp2[p*DDIM + c] = {e_{2p}[c], e_{2p+1}[c]}
//   [NPAIR*DDIM*2 .. +KNUM)  float   ssq[k] (adjacent even/odd floats = packed ull pairs)
extern __shared__ float s_dyn[];

__global__ __launch_bounds__(THREADS, 1)
void vq_main_kernel(const float* __restrict__ z_e,
                    const float* __restrict__ emb,
                    float* __restrict__ zq_out,
                    float* __restrict__ idx_out)
{
    float2* sp2 = (float2*)s_dyn;                  // NPAIR*DDIM float2
    float*  ssq = s_dyn + 2 * NPAIR * DDIM;        // KNUM floats
    const int tid = threadIdx.x;

    // Load embedding, transposing to pair-interleaved layout.
    // Each thread reads float4 (4 dims of one code k) and scatters lane (k&1).
    for (int i = tid; i < KNUM * DDIM / 4; i += blockDim.x) {
        int k  = i >> 4;            // code (16 float4 per code)
        int c4 = (i & 15) << 2;     // starting dim
        float4 v = ((const float4*)emb)[i];
        int p = k >> 1, l = k & 1;
        float* dst = (float*)(sp2 + p * DDIM);
        dst[(c4 + 0) * 2 + l] = v.x;
        dst[(c4 + 1) * 2 + l] = v.y;
        dst[(c4 + 2) * 2 + l] = v.z;
        dst[(c4 + 3) * 2 + l] = v.w;
    }
    __syncthreads();

    // ||e_k||^2 exactly as jnp.sum(emb*emb, axis=1): sequential, UNFUSED.
    for (int k = tid; k < KNUM; k += blockDim.x) {
        const float* e = (const float*)(sp2 + (k >> 1) * DDIM) + (k & 1);
        float s = 0.f;
        for (int d = 0; d < DDIM; d++) {
            float pr = __fmul_rn(e[2 * d], e[2 * d]);
            s = __fadd_rn(s, pr);
        }
        ssq[k] = s;
    }
    __syncthreads();

    const int row = blockIdx.x * THREADS + tid;
    const bool active = (row < NROWS);
    const int n  = row >> 12;
    const int hw = row & 4095;

    // Load x[64] (NCHW: channel stride HW; consecutive tids coalesced)
    float x[DDIM];
    if (active) {
        const float* xin = z_e + (size_t)n * (DDIM * HW) + hw;
        #pragma unroll
        for (int c = 0; c < DDIM; c++) x[c] = xin[c * HW];
    } else {
        #pragma unroll
        for (int c = 0; c < DDIM; c++) x[c] = 0.f;
    }

    // ||x||^2: sequential, UNFUSED (reference order).
    float sx = 0.f;
    #pragma unroll
    for (int c = 0; c < DDIM; c++) {
        float pr = __fmul_rn(x[c], x[c]);
        sx = __fadd_rn(sx, pr);
    }

    const ull sx2     = pack2(sx, sx);
    const ull negtwo2 = pack2(-2.0f, -2.0f);
    const ull* ssq2   = (const ull*)ssq;

    // Packed argmin: lane0 = even code, lane1 = odd code.
    // Each lane is the exact sequential fmaf chain d=0..63 (bit-identical to scalar).
    float best0 = 3.4e38f, best1 = 3.4e38f;
    int bi0 = 0, bi1 = 1;

    for (int pb = 0; pb < NPAIR; pb += GP) {
        ull acc[GP];
        #pragma unroll
        for (int j = 0; j < GP; j++) acc[j] = 0ull;

        const ulonglong2* eb = (const ulonglong2*)(sp2 + pb * DDIM);
        #pragma unroll
        for (int c2 = 0; c2 < DDIM / 2; c2++) {
            ull xa = pack2(x[2 * c2],     x[2 * c2]);
            ull xb = pack2(x[2 * c2 + 1], x[2 * c2 + 1]);
            #pragma unroll
            for (int j = 0; j < GP; j++) {
                // 16B: {e_even[c], e_odd[c], e_even[c+1], e_odd[c+1]}
                ulonglong2 ee = eb[j * (DDIM / 2) + c2];
                acc[j] = ffma2(xa, ee.x, acc[j]);   // dim 2*c2
                acc[j] = ffma2(xb, ee.y, acc[j]);   // dim 2*c2+1
            }
        }
        #pragma unroll
        for (int j = 0; j < GP; j++) {
            // d = fl( fl(sx+ssq) - 2*dot );  2*dot exact => single fma rounding identical
            ull t2 = fadd2(sx2, ssq2[pb + j]);
            ull d2 = ffma2(acc[j], negtwo2, t2);
            float d0, d1;
            unpack2(d2, d0, d1);
            int k0 = 2 * (pb + j);
            if (d0 < best0) { best0 = d0; bi0 = k0; }
            if (d1 < best1) { best1 = d1; bi1 = k0 + 1; }
        }
    }
    // Merge lanes; exact tie -> lower index (could be the odd lane).
    int bidx = (best1 < best0 || (best1 == best0 && bi1 < bi0)) ? bi1 : bi0;

    // Epilogue: gather z_q, straight-through, loss partial, index, count
    float lsum = 0.f;
    if (active) {
        const float* eb = (const float*)(sp2 + (bidx >> 1) * DDIM) + (bidx & 1);
        float* zq = zq_out + (size_t)n * (DDIM * HW) + hw;
        #pragma unroll
        for (int c = 0; c < DDIM; c++) {
            float v = eb[2 * c];
            float diff = __fsub_rn(v, x[c]);
            zq[c * HW] = __fadd_rn(x[c], diff);
            lsum = fmaf(diff, diff, lsum);
        }
        if (idx_out) idx_out[row] = (float)bidx;
        atomicAdd(&g_counts[bidx], 1u);
    }

    // Block-reduce loss -> one double atomic per CTA
    #pragma unroll
    for (int o = 16; o > 0; o >>= 1)
        lsum += __shfl_down_sync(0xffffffffu, lsum, o);
    __shared__ float wsum[THREADS / 32];
    if ((tid & 31) == 0) wsum[tid >> 5] = lsum;
    __syncthreads();
    if (tid == 0) {
        float t = 0.f;
        #pragma unroll
        for (int w = 0; w < THREADS / 32; w++) t += wsum[w];
        atomicAdd(&g_loss_sum, (double)t);
    }
}

__global__ void vq_finalize_kernel(float* loss_out, float* perp_out) {
    __shared__ double sh[KNUM];
    const int t = threadIdx.x;
    double c = (double)g_counts[t];
    double p = c / (double)NROWS;
    sh[t] = p * log(p + 1e-10);
    __syncthreads();
    for (int s = KNUM / 2; s > 0; s >>= 1) {
        if (t < s) sh[t] += sh[t + s];
        __syncthreads();
    }
    if (t == 0) {
        if (perp_out) *perp_out = (float)exp(-sh[0]);
        if (loss_out) *loss_out = (float)(0.25 * g_loss_sum / (double)((size_t)NROWS * DDIM));
    }
}

extern "C" void kernel_launch(void* const* d_in, const int* in_sizes, int n_in,
                              void* d_out, int out_size) {
    const float* z_e = (const float*)d_in[0];
    const float* emb = (const float*)d_in[1];
    float* out = (float*)d_out;

    float* zq_out = out;
    float* loss_p = nullptr;
    float* perp_p = nullptr;
    float* idx_p  = nullptr;
    const int ZQ = NB * DDIM * HW;   // 4194304
    if (out_size >= ZQ + 2 + NROWS) {
        loss_p = out + ZQ;
        perp_p = out + ZQ + 1;
        idx_p  = out + ZQ + 2;
    }

    const int smem_bytes = (2 * NPAIR * DDIM + KNUM) * (int)sizeof(float);
    cudaFuncSetAttribute(vq_main_kernel,
                         cudaFuncAttributeMaxDynamicSharedMemorySize, smem_bytes);

    vq_init_kernel<<<1, KNUM>>>();
    vq_main_kernel<<<148, THREADS, smem_bytes>>>(z_e, emb, zq_out, idx_p);
    vq_finalize_kernel<<<1, KNUM>>>(loss_p, perp_p);
}

// round 11
// speedup vs baseline: 1.0250x; 1.0250x over previous
#include <cuda_runtime.h>
#include <cuda_bf16.h>
#include <math.h>
#include <stdint.h>

#define KNUM 512
#define DDIM 64
#define NROWS 65536
#define HW 4096
#define NB 16
#define MTILE 128
#define NTILES 512
#define THREADS 512
#define CAP 32
#define MARGIN 1.5e-4f

typedef unsigned long long ull;

// ---------------- device scratch ----------------
__device__ double g_loss_sum;
__device__ unsigned int g_counts[KNUM];
__device__ float ssq_g[KNUM];
// B fragments packed per (code, lane%4): 8 u32 words = 16 bf16 covering all 4 k-steps
__device__ uint32_t bfrag_hi_g[KNUM * 4 * 8];
__device__ uint32_t bfrag_lo_g[KNUM * 4 * 8];

// ---------------- smem layout (bytes) ----------------
#define BHI_OFF  0          // 65536
#define BLO_OFF  65536      // 65536
#define XS_OFF   131072     // 128*64 f32 = 32768   x_s[c*128+row]
#define SSQ_OFF  163840     // 512 f32 = 2048
#define SX_OFF   165888     // 128 f32 = 512
#define CL_OFF   166400     // 128*CAP u32 = 16384
#define CC_OFF   182784     // 128 u32 = 512
#define SLOT_OFF 183296     // 128 ull = 1024
#define WS_OFF   184320     // 16 f32 = 64
#define SMEM_TOTAL 184384
#define ZSEL_OFF BHI_OFF    // overlays dead B region after rescue: 64*128 f32

__device__ __forceinline__ void mma16816(float d[4], const uint32_t a[4],
                                         uint32_t b0, uint32_t b1) {
    asm volatile(
        "mma.sync.aligned.m16n8k16.row.col.f32.bf16.bf16.f32 "
        "{%0,%1,%2,%3}, {%4,%5,%6,%7}, {%8,%9}, {%0,%1,%2,%3};"
        : "+f"(d[0]), "+f"(d[1]), "+f"(d[2]), "+f"(d[3])
        : "r"(a[0]), "r"(a[1]), "r"(a[2]), "r"(a[3]), "r"(b0), "r"(b1));
}

__device__ __forceinline__ uint32_t pack_bf2(float lo, float hi) {
    __nv_bfloat162 p;
    p.x = __float2bfloat16(lo);
    p.y = __float2bfloat16(hi);
    return *(uint32_t*)&p;
}

// ---------------- prep: exact ssq + hi/lo B fragment packing ----------------
__global__ void vq_prep_kernel(const float* __restrict__ emb) {
    int k = threadIdx.x;   // 512 threads, one code each
    g_counts[k] = 0u;
    if (k == 0) g_loss_sum = 0.0;
    const float* e = emb + k * DDIM;
    float s = 0.f;
    __nv_bfloat16 hb[DDIM], lb[DDIM];
    for (int d = 0; d < DDIM; d++) {
        float v = e[d];
        s = __fadd_rn(s, __fmul_rn(v, v));   // reference order: unfused sequential
        hb[d] = __float2bfloat16(v);
        lb[d] = __float2bfloat16(v - __bfloat162float(hb[d]));
    }
    ssq_g[k] = s;
    for (int q = 0; q < 4; q++) {
        for (int w = 0; w < 8; w++) {
            int ks = w >> 1, hf = w & 1;
            int d0 = ks * 16 + hf * 8 + q * 2;
            __nv_bfloat162 ph; ph.x = hb[d0]; ph.y = hb[d0 + 1];
            __nv_bfloat162 pl; pl.x = lb[d0]; pl.y = lb[d0 + 1];
            bfrag_hi_g[(k * 4 + q) * 8 + w] = *(uint32_t*)&ph;
            bfrag_lo_g[(k * 4 + q) * 8 + w] = *(uint32_t*)&pl;
        }
    }
}

// ---------------- exact rescue evaluation (bit-exact reference pipeline) ----
__device__ __forceinline__ void eval_exact(int k, int row, const float* emb,
                                           const float* x_s, const float* sx_s,
                                           const float* ssq_s, ull* slot) {
    const float4* eg = (const float4*)(emb + k * DDIM);
    float acc = 0.f;
    #pragma unroll
    for (int i = 0; i < 16; i++) {
        float4 e = eg[i];
        acc = fmaf(x_s[(4 * i + 0) * 128 + row], e.x, acc);
        acc = fmaf(x_s[(4 * i + 1) * 128 + row], e.y, acc);
        acc = fmaf(x_s[(4 * i + 2) * 128 + row], e.z, acc);
        acc = fmaf(x_s[(4 * i + 3) * 128 + row], e.w, acc);
    }
    float d = __fadd_rn(sx_s[row], ssq_s[k]);
    d = __fsub_rn(d, __fmul_rn(2.0f, acc));
    uint32_t ui = __float_as_uint(d);
    uint32_t key = ui ^ ((ui & 0x80000000u) ? 0xFFFFFFFFu : 0x80000000u);
    atomicMin(&slot[row], ((ull)key << 32) | (uint32_t)k);
}

// ---------------- main ----------------
extern __shared__ char smem[];

__global__ __launch_bounds__(THREADS, 1)
void vq_main_kernel(const float* __restrict__ z_e,
                    const float* __restrict__ emb,
                    float* __restrict__ zq_out,
                    float* __restrict__ idx_out)
{
    const int tid  = threadIdx.x;
    const int wid  = tid >> 5;
    const int lane = tid & 31;
    const int wq   = lane & 3;
    const int wr   = lane >> 2;
    const int tile = blockIdx.x;
    const int n    = tile >> 5;
    const int hw0  = (tile & 31) * MTILE;
    const size_t gbase = (size_t)n * (DDIM * HW) + hw0;

    float* x_s    = (float*)(smem + XS_OFF);
    float* ssq_s  = (float*)(smem + SSQ_OFF);
    float* sx_s   = (float*)(smem + SX_OFF);
    uint32_t* clist = (uint32_t*)(smem + CL_OFF);
    uint32_t* ccnt  = (uint32_t*)(smem + CC_OFF);
    ull*   slot   = (ull*)(smem + SLOT_OFF);
    float* wsum   = (float*)(smem + WS_OFF);

    if (tid < MTILE) { slot[tid] = ~0ull; ccnt[tid] = 0u; }

    // Stage B fragments into smem (128 KB, L2-broadcast across CTAs)
    {
        const uint4* gh = (const uint4*)bfrag_hi_g;
        const uint4* gl = (const uint4*)bfrag_lo_g;
        uint4* sh = (uint4*)(smem + BHI_OFF);
        uint4* sl = (uint4*)(smem + BLO_OFF);
        for (int i = tid; i < KNUM * 4 * 8 / 4; i += THREADS) {
            sh[i] = gh[i];
            sl[i] = gl[i];
        }
    }
    // x tile (coalesced) -> x_s[c*128+row]
    for (int i = tid; i < MTILE * DDIM; i += THREADS) {
        int c = i >> 7, r = i & 127;
        x_s[c * 128 + r] = z_e[gbase + (size_t)c * HW + r];
    }
    ssq_s[tid] = ssq_g[tid];
    __syncthreads();

    // exact ||x||^2 per row (sequential, UNFUSED -- reference order)
    if (tid < MTILE) {
        float s = 0.f;
        for (int c = 0; c < DDIM; c++) {
            float xv = x_s[c * 128 + tid];
            s = __fadd_rn(s, __fmul_rn(xv, xv));
        }
        sx_s[tid] = s;
    }

    // A fragments (hi/lo bf16) for this warp's 16 rows, all 4 k-steps
    const int r0   = (wid & 7) * 16;
    const int half = wid >> 3;           // col half: cols half*256 .. +255
    const int rA = r0 + wr, rB = rA + 8;
    uint32_t Ahi[4][4], Alo[4][4];
    #pragma unroll
    for (int ks = 0; ks < 4; ks++) {
        #pragma unroll
        for (int h = 0; h < 2; h++) {
            int c0 = ks * 16 + h * 8 + wq * 2;
            float fA0 = x_s[c0 * 128 + rA], fA1 = x_s[(c0 + 1) * 128 + rA];
            float fB0 = x_s[c0 * 128 + rB], fB1 = x_s[(c0 + 1) * 128 + rB];
            __nv_bfloat16 hA0 = __float2bfloat16(fA0), hA1 = __float2bfloat16(fA1);
            __nv_bfloat16 hB0 = __float2bfloat16(fB0), hB1 = __float2bfloat16(fB1);
            {
                __nv_bfloat162 p; p.x = hA0; p.y = hA1;
                Ahi[ks][2 * h] = *(uint32_t*)&p;
                __nv_bfloat162 q2; q2.x = hB0; q2.y = hB1;
                Ahi[ks][2 * h + 1] = *(uint32_t*)&q2;
            }
            Alo[ks][2 * h]     = pack_bf2(fA0 - __bfloat162float(hA0),
                                          fA1 - __bfloat162float(hA1));
            Alo[ks][2 * h + 1] = pack_bf2(fB0 - __bfloat162float(hB0),
                                          fB1 - __bfloat162float(hB1));
        }
    }

    // MMA filter: per group of 64 cols, two-phase flush (min, then insert)
    float m0 = 3.4e38f, m1 = 3.4e38f;
    for (int g = 0; g < 4; g++) {
        float acc[8][4];
        #pragma unroll
        for (int nf = 0; nf < 8; nf++)
            #pragma unroll
            for (int j = 0; j < 4; j++) acc[nf][j] = 0.f;

        const int colbase0 = half * 256 + g * 64;
        #pragma unroll
        for (int nf = 0; nf < 8; nf++) {
            int col = colbase0 + nf * 8 + wr;   // B operand column for this lane
            const uint4* bh = (const uint4*)(smem + BHI_OFF + (((col << 2) + wq) << 5));
            const uint4* bl = (const uint4*)(smem + BLO_OFF + (((col << 2) + wq) << 5));
            uint4 h0 = bh[0], h1 = bh[1];
            uint4 l0 = bl[0], l1 = bl[1];
            // 3-term fp32-emulating accumulation, 4 k-steps
            mma16816(acc[nf], Ahi[0], h0.x, h0.y);
            mma16816(acc[nf], Alo[0], h0.x, h0.y);
            mma16816(acc[nf], Ahi[0], l0.x, l0.y);
            mma16816(acc[nf], Ahi[1], h0.z, h0.w);
            mma16816(acc[nf], Alo[1], h0.z, h0.w);
            mma16816(acc[nf], Ahi[1], l0.z, l0.w);
            mma16816(acc[nf], Ahi[2], h1.x, h1.y);
            mma16816(acc[nf], Alo[2], h1.x, h1.y);
            mma16816(acc[nf], Ahi[2], l1.x, l1.y);
            mma16816(acc[nf], Ahi[3], h1.z, h1.w);
            mma16816(acc[nf], Alo[3], h1.z, h1.w);
            mma16816(acc[nf], Ahi[3], l1.z, l1.w);
        }
        // phase 1: d~ = ssq - 2*dot, track row mins
        #pragma unroll
        for (int nf = 0; nf < 8; nf++) {
            int c0 = colbase0 + nf * 8 + wq * 2;   // C-fragment columns
            float d0 = fmaf(acc[nf][0], -2.f, ssq_s[c0]);
            float d1 = fmaf(acc[nf][1], -2.f, ssq_s[c0 + 1]);
            float d2 = fmaf(acc[nf][2], -2.f, ssq_s[c0]);
            float d3 = fmaf(acc[nf][3], -2.f, ssq_s[c0 + 1]);
            acc[nf][0] = d0; acc[nf][1] = d1; acc[nf][2] = d2; acc[nf][3] = d3;
            m0 = fminf(m0, fminf(d0, d1));
            m1 = fminf(m1, fminf(d2, d3));
        }
        // row-min across the 4 quad lanes sharing each row
        m0 = fminf(m0, __shfl_xor_sync(0xffffffffu, m0, 1));
        m0 = fminf(m0, __shfl_xor_sync(0xffffffffu, m0, 2));
        m1 = fminf(m1, __shfl_xor_sync(0xffffffffu, m1, 1));
        m1 = fminf(m1, __shfl_xor_sync(0xffffffffu, m1, 2));
        // phase 2: insert candidates within margin of running min
        float t0 = m0 + MARGIN, t1 = m1 + MARGIN;
        #pragma unroll
        for (int nf = 0; nf < 8; nf++) {
            int c0 = colbase0 + nf * 8 + wq * 2;
            if (acc[nf][0] <= t0) { uint32_t c = atomicAdd(&ccnt[rA], 1u); if (c < CAP) clist[rA * CAP + c] = c0; }
            if (acc[nf][1] <= t0) { uint32_t c = atomicAdd(&ccnt[rA], 1u); if (c < CAP) clist[rA * CAP + c] = c0 + 1; }
            if (acc[nf][2] <= t1) { uint32_t c = atomicAdd(&ccnt[rB], 1u); if (c < CAP) clist[rB * CAP + c] = c0; }
            if (acc[nf][3] <= t1) { uint32_t c = atomicAdd(&ccnt[rB], 1u); if (c < CAP) clist[rB * CAP + c] = c0 + 1; }
        }
    }
    __syncthreads();

    // Rescue: exact re-evaluation of all listed candidates (4 threads per row)
    {
        int row = tid >> 2, e0 = tid & 3;
        int cnt = (int)ccnt[row];
        if (cnt <= CAP) {
            for (int i = e0; i < cnt; i += 4)
                eval_exact((int)clist[row * CAP + i], row, emb, x_s, sx_s, ssq_s, slot);
        } else {
            // overflow fallback (statistically never): exact full scan
            for (int k = e0; k < KNUM; k += 4)
                eval_exact(k, row, emb, x_s, sx_s, ssq_s, slot);
        }
    }
    __syncthreads();

    // Stage selected codes into smem (overlays dead B region)
    float* zsel = (float*)(smem + ZSEL_OFF);   // zsel[c*128+row]
    if (tid < MTILE) {
        int kk = (int)(uint32_t)(slot[tid] & 0xFFFFFFFFull);
        const float4* eg = (const float4*)(emb + kk * DDIM);
        #pragma unroll
        for (int i = 0; i < 16; i++) {
            float4 e = eg[i];
            zsel[(4 * i + 0) * 128 + tid] = e.x;
            zsel[(4 * i + 1) * 128 + tid] = e.y;
            zsel[(4 * i + 2) * 128 + tid] = e.z;
            zsel[(4 * i + 3) * 128 + tid] = e.w;
        }
        if (idx_out) idx_out[tile * MTILE + tid] = (float)kk;
        atomicAdd(&g_counts[kk], 1u);
    }
    __syncthreads();

    // z_q straight-through (coalesced) + commitment loss partial
    float lsum = 0.f;
    for (int i = tid; i < MTILE * DDIM; i += THREADS) {
        int c = i >> 7, r = i & 127;
        float v  = zsel[c * 128 + r];
        float xv = x_s[c * 128 + r];
        float diff = __fsub_rn(v, xv);
        zq_out[gbase + (size_t)c * HW + r] = __fadd_rn(xv, diff);
        lsum = fmaf(diff, diff, lsum);
    }
    #pragma unroll
    for (int o = 16; o > 0; o >>= 1)
        lsum += __shfl_down_sync(0xffffffffu, lsum, o);
    if (lane == 0) wsum[wid] = lsum;
    __syncthreads();
    if (tid == 0) {
        float t = 0.f;
        #pragma unroll
        for (int w = 0; w < THREADS / 32; w++) t += wsum[w];
        atomicAdd(&g_loss_sum, (double)t);
    }
}

__global__ void vq_finalize_kernel(float* loss_out, float* perp_out) {
    __shared__ double sh[KNUM];
    const int t = threadIdx.x;
    double c = (double)g_counts[t];
    double p = c / (double)NROWS;
    sh[t] = p * log(p + 1e-10);
    __syncthreads();
    for (int s = KNUM / 2; s > 0; s >>= 1) {
        if (t < s) sh[t] += sh[t + s];
        __syncthreads();
    }
    if (t == 0) {
        if (perp_out) *perp_out = (float)exp(-sh[0]);
        if (loss_out) *loss_out = (float)(0.25 * g_loss_sum / (double)((size_t)NROWS * DDIM));
    }
}

extern "C" void kernel_launch(void* const* d_in, const int* in_sizes, int n_in,
                              void* d_out, int out_size) {
    const float* z_e = (const float*)d_in[0];
    const float* emb = (const float*)d_in[1];
    float* out = (float*)d_out;

    float* zq_out = out;
    float* loss_p = nullptr;
    float* perp_p = nullptr;
    float* idx_p  = nullptr;
    const int ZQ = NB * DDIM * HW;   // 4194304
    if (out_size >= ZQ + 2 + NROWS) {
        loss_p = out + ZQ;
        perp_p = out + ZQ + 1;
        idx_p  = out + ZQ + 2;
    }

    cudaFuncSetAttribute(vq_main_kernel,
                         cudaFuncAttributeMaxDynamicSharedMemorySize, SMEM_TOTAL);

    vq_prep_kernel<<<1, KNUM>>>(emb);
    vq_main_kernel<<<NTILES, THREADS, SMEM_TOTAL>>>(z_e, emb, zq_out, idx_p);
    vq_finalize_kernel<<<1, KNUM>>>(loss_p, perp_p);
}

// round 12
// speedup vs baseline: 1.5412x; 1.5036x over previous
#include <cuda_runtime.h>
#include <cuda_bf16.h>
#include <math.h>
#include <stdint.h>

#define KNUM 512
#define DDIM 64
#define NROWS 65536
#define HW 4096
#define NB 16
#define MTILE 128
#define NTILES 512
#define THREADS 512
#define CAP 48
#define MARGIN 2.0e-3f

typedef unsigned long long ull;

// ---------------- device scratch ----------------
__device__ double g_loss_sum;
__device__ unsigned int g_counts[KNUM];
__device__ float ssq_g[KNUM];
// B fragments, word-major: bfrag_hi_g[w*2048 + k*4 + q], w in [0,8), q = lane&3
// word w covers dims d0 = (w>>1)*16 + (w&1)*8 + q*2, d0+1 (bf16x2)
__device__ uint32_t bfrag_hi_g[8 * KNUM * 4];

// ---------------- smem layout (bytes) ----------------
#define BHI_OFF  0          // 65536 (8*2048 u32)
#define XS_OFF   65536      // 128*64 f32 = 32768   x_s[c*128+row]
#define SSQ_OFF  98304      // 512 f32 = 2048
#define SX_OFF   100352     // 128 f32 = 512
#define CL_OFF   100864     // 128*CAP u32 = 24576
#define CC_OFF   125440     // 128 u32 = 512
#define SLOT_OFF 125952     // 128 ull = 1024
#define WS_OFF   126976     // 16 f32 = 64
#define SMEM_TOTAL 127040
#define ZSEL_OFF BHI_OFF    // overlays dead B region after rescue: 64*128 f32

__device__ __forceinline__ void mma16816(float d[4], const uint32_t a[4],
                                         uint32_t b0, uint32_t b1) {
    asm volatile(
        "mma.sync.aligned.m16n8k16.row.col.f32.bf16.bf16.f32 "
        "{%0,%1,%2,%3}, {%4,%5,%6,%7}, {%8,%9}, {%0,%1,%2,%3};"
        : "+f"(d[0]), "+f"(d[1]), "+f"(d[2]), "+f"(d[3])
        : "r"(a[0]), "r"(a[1]), "r"(a[2]), "r"(a[3]), "r"(b0), "r"(b1));
}

// ---------------- prep: parallel (512 blocks x 32 threads) ----------------
__global__ void vq_prep_kernel(const float* __restrict__ emb) {
    const int k = blockIdx.x;
    const int t = threadIdx.x;
    if (t == 0) {
        g_counts[k] = 0u;
        if (k == 0) g_loss_sum = 0.0;
        // exact ssq: sequential, UNFUSED (reference order)
        const float* e = emb + k * DDIM;
        float s = 0.f;
        for (int d = 0; d < DDIM; d++)
            s = __fadd_rn(s, __fmul_rn(e[d], e[d]));
        ssq_g[k] = s;
    }
    const int q = t & 3, w = t >> 2;
    const int d0 = (w >> 1) * 16 + (w & 1) * 8 + q * 2;
    __nv_bfloat162 p;
    p.x = __float2bfloat16(emb[k * DDIM + d0]);
    p.y = __float2bfloat16(emb[k * DDIM + d0 + 1]);
    bfrag_hi_g[w * (KNUM * 4) + k * 4 + q] = *(uint32_t*)&p;
}

// ---------------- exact rescue evaluation (bit-exact reference pipeline) ----
__device__ __forceinline__ void eval_exact(int k, int row, const float* emb,
                                           const float* x_s, const float* sx_s,
                                           const float* ssq_s, ull* slot) {
    const float4* eg = (const float4*)(emb + k * DDIM);
    float acc = 0.f;
    #pragma unroll
    for (int i = 0; i < 16; i++) {
        float4 e = eg[i];
        acc = fmaf(x_s[(4 * i + 0) * 128 + row], e.x, acc);
        acc = fmaf(x_s[(4 * i + 1) * 128 + row], e.y, acc);
        acc = fmaf(x_s[(4 * i + 2) * 128 + row], e.z, acc);
        acc = fmaf(x_s[(4 * i + 3) * 128 + row], e.w, acc);
    }
    float d = __fadd_rn(sx_s[row], ssq_s[k]);
    d = __fsub_rn(d, __fmul_rn(2.0f, acc));
    uint32_t ui = __float_as_uint(d);
    uint32_t key = ui ^ ((ui & 0x80000000u) ? 0xFFFFFFFFu : 0x80000000u);
    atomicMin(&slot[row], ((ull)key << 32) | (uint32_t)k);
}

// ---------------- main ----------------
extern __shared__ char smem[];

__global__ __launch_bounds__(THREADS, 1)
void vq_main_kernel(const float* __restrict__ z_e,
                    const float* __restrict__ emb,
                    float* __restrict__ zq_out,
                    float* __restrict__ idx_out)
{
    const int tid  = threadIdx.x;
    const int wid  = tid >> 5;
    const int lane = tid & 31;
    const int wq   = lane & 3;
    const int wr   = lane >> 2;
    const int tile = blockIdx.x;
    const int n    = tile >> 5;
    const int hw0  = (tile & 31) * MTILE;
    const size_t gbase = (size_t)n * (DDIM * HW) + hw0;

    float* x_s    = (float*)(smem + XS_OFF);
    float* ssq_s  = (float*)(smem + SSQ_OFF);
    float* sx_s   = (float*)(smem + SX_OFF);
    uint32_t* clist = (uint32_t*)(smem + CL_OFF);
    uint32_t* ccnt  = (uint32_t*)(smem + CC_OFF);
    ull*   slot   = (ull*)(smem + SLOT_OFF);
    float* wsum   = (float*)(smem + WS_OFF);
    const uint32_t* sB = (const uint32_t*)(smem + BHI_OFF);

    if (tid < MTILE) { slot[tid] = ~0ull; ccnt[tid] = 0u; }

    // Stage B fragments into smem (64 KB, linear copy)
    {
        const uint4* gh = (const uint4*)bfrag_hi_g;
        uint4* sh = (uint4*)(smem + BHI_OFF);
        for (int i = tid; i < 8 * KNUM; i += THREADS) sh[i] = gh[i];
    }
    // x tile (coalesced) -> x_s[c*128+row]
    for (int i = tid; i < MTILE * DDIM; i += THREADS) {
        int c = i >> 7, r = i & 127;
        x_s[c * 128 + r] = z_e[gbase + (size_t)c * HW + r];
    }
    ssq_s[tid] = ssq_g[tid];
    __syncthreads();

    // exact ||x||^2 per row (sequential, UNFUSED -- reference order)
    if (tid < MTILE) {
        float s = 0.f;
        for (int c = 0; c < DDIM; c++) {
            float xv = x_s[c * 128 + tid];
            s = __fadd_rn(s, __fmul_rn(xv, xv));
        }
        sx_s[tid] = s;
    }

    // A fragments (hi bf16) for this warp's 16 rows, all 4 k-steps
    const int r0   = (wid & 7) * 16;
    const int half = wid >> 3;           // col half: cols half*256 .. +255
    const int rA = r0 + wr, rB = rA + 8;
    uint32_t Ahi[4][4];
    #pragma unroll
    for (int ks = 0; ks < 4; ks++) {
        #pragma unroll
        for (int h = 0; h < 2; h++) {
            int c0 = ks * 16 + h * 8 + wq * 2;
            __nv_bfloat162 pa, pb;
            pa.x = __float2bfloat16(x_s[c0 * 128 + rA]);
            pa.y = __float2bfloat16(x_s[(c0 + 1) * 128 + rA]);
            pb.x = __float2bfloat16(x_s[c0 * 128 + rB]);
            pb.y = __float2bfloat16(x_s[(c0 + 1) * 128 + rB]);
            Ahi[ks][2 * h]     = *(uint32_t*)&pa;
            Ahi[ks][2 * h + 1] = *(uint32_t*)&pb;
        }
    }

    // MMA filter (bf16 hi*hi only): per group of 64 cols, min then insert
    float m0 = 3.4e38f, m1 = 3.4e38f;
    for (int g = 0; g < 4; g++) {
        float acc[8][4];
        #pragma unroll
        for (int nf = 0; nf < 8; nf++)
            #pragma unroll
            for (int j = 0; j < 4; j++) acc[nf][j] = 0.f;

        const int colbase0 = half * 256 + g * 64;
        #pragma unroll
        for (int nf = 0; nf < 8; nf++) {
            int bi = ((colbase0 + nf * 8 + wr) << 2) + wq;
            // word-major, conflict-free: bank = 4*wr+wq = lane id
            uint32_t b0 = sB[0 * 2048 + bi], b1 = sB[1 * 2048 + bi];
            uint32_t b2 = sB[2 * 2048 + bi], b3 = sB[3 * 2048 + bi];
            uint32_t b4 = sB[4 * 2048 + bi], b5 = sB[5 * 2048 + bi];
            uint32_t b6 = sB[6 * 2048 + bi], b7 = sB[7 * 2048 + bi];
            mma16816(acc[nf], Ahi[0], b0, b1);
            mma16816(acc[nf], Ahi[1], b2, b3);
            mma16816(acc[nf], Ahi[2], b4, b5);
            mma16816(acc[nf], Ahi[3], b6, b7);
        }
        // phase 1: d~ = ssq - 2*dot, track row mins
        #pragma unroll
        for (int nf = 0; nf < 8; nf++) {
            int c0 = colbase0 + nf * 8 + wq * 2;
            float d0 = fmaf(acc[nf][0], -2.f, ssq_s[c0]);
            float d1 = fmaf(acc[nf][1], -2.f, ssq_s[c0 + 1]);
            float d2 = fmaf(acc[nf][2], -2.f, ssq_s[c0]);
            float d3 = fmaf(acc[nf][3], -2.f, ssq_s[c0 + 1]);
            acc[nf][0] = d0; acc[nf][1] = d1; acc[nf][2] = d2; acc[nf][3] = d3;
            m0 = fminf(m0, fminf(d0, d1));
            m1 = fminf(m1, fminf(d2, d3));
        }
        // row-min across the 4 quad lanes sharing each row
        m0 = fminf(m0, __shfl_xor_sync(0xffffffffu, m0, 1));
        m0 = fminf(m0, __shfl_xor_sync(0xffffffffu, m0, 2));
        m1 = fminf(m1, __shfl_xor_sync(0xffffffffu, m1, 1));
        m1 = fminf(m1, __shfl_xor_sync(0xffffffffu, m1, 2));
        // phase 2: insert candidates within margin of running min
        float t0 = m0 + MARGIN, t1 = m1 + MARGIN;
        #pragma unroll
        for (int nf = 0; nf < 8; nf++) {
            int c0 = colbase0 + nf * 8 + wq * 2;
            if (acc[nf][0] <= t0) { uint32_t c = atomicAdd(&ccnt[rA], 1u); if (c < CAP) clist[rA * CAP + c] = c0; }
            if (acc[nf][1] <= t0) { uint32_t c = atomicAdd(&ccnt[rA], 1u); if (c < CAP) clist[rA * CAP + c] = c0 + 1; }
            if (acc[nf][2] <= t1) { uint32_t c = atomicAdd(&ccnt[rB], 1u); if (c < CAP) clist[rB * CAP + c] = c0; }
            if (acc[nf][3] <= t1) { uint32_t c = atomicAdd(&ccnt[rB], 1u); if (c < CAP) clist[rB * CAP + c] = c0 + 1; }
        }
    }
    __syncthreads();

    // Rescue: exact re-evaluation of all listed candidates (4 threads per row)
    {
        int row = tid >> 2, e0 = tid & 3;
        int cnt = (int)ccnt[row];
        if (cnt <= CAP) {
            for (int i = e0; i < cnt; i += 4)
                eval_exact((int)clist[row * CAP + i], row, emb, x_s, sx_s, ssq_s, slot);
        } else {
            // overflow fallback (statistically never): exact full scan
            for (int k = e0; k < KNUM; k += 4)
                eval_exact(k, row, emb, x_s, sx_s, ssq_s, slot);
        }
    }
    __syncthreads();

    // Stage selected codes into smem (overlays dead B region)
    float* zsel = (float*)(smem + ZSEL_OFF);   // zsel[c*128+row]
    if (tid < MTILE) {
        int kk = (int)(uint32_t)(slot[tid] & 0xFFFFFFFFull);
        const float4* eg = (const float4*)(emb + kk * DDIM);
        #pragma unroll
        for (int i = 0; i < 16; i++) {
            float4 e = eg[i];
            zsel[(4 * i + 0) * 128 + tid] = e.x;
            zsel[(4 * i + 1) * 128 + tid] = e.y;
            zsel[(4 * i + 2) * 128 + tid] = e.z;
            zsel[(4 * i + 3) * 128 + tid] = e.w;
        }
        if (idx_out) idx_out[tile * MTILE + tid] = (float)kk;
        atomicAdd(&g_counts[kk], 1u);
    }
    __syncthreads();

    // z_q straight-through (coalesced) + commitment loss partial
    float lsum = 0.f;
    for (int i = tid; i < MTILE * DDIM; i += THREADS) {
        int c = i >> 7, r = i & 127;
        float v  = zsel[c * 128 + r];
        float xv = x_s[c * 128 + r];
        float diff = __fsub_rn(v, xv);
        zq_out[gbase + (size_t)c * HW + r] = __fadd_rn(xv, diff);
        lsum = fmaf(diff, diff, lsum);
    }
    #pragma unroll
    for (int o = 16; o > 0; o >>= 1)
        lsum += __shfl_down_sync(0xffffffffu, lsum, o);
    if (lane == 0) wsum[wid] = lsum;
    __syncthreads();
    if (tid == 0) {
        float t = 0.f;
        #pragma unroll
        for (int w = 0; w < THREADS / 32; w++) t += wsum[w];
        atomicAdd(&g_loss_sum, (double)t);
    }
}

__global__ void vq_finalize_kernel(float* loss_out, float* perp_out) {
    __shared__ double sh[KNUM];
    const int t = threadIdx.x;
    double c = (double)g_counts[t];
    double p = c / (double)NROWS;
    sh[t] = p * log(p + 1e-10);
    __syncthreads();
    for (int s = KNUM / 2; s > 0; s >>= 1) {
        if (t < s) sh[t] += sh[t + s];
        __syncthreads();
    }
    if (t == 0) {
        if (perp_out) *perp_out = (float)exp(-sh[0]);
        if (loss_out) *loss_out = (float)(0.25 * g_loss_sum / (double)((size_t)NROWS * DDIM));
    }
}

extern "C" void kernel_launch(void* const* d_in, const int* in_sizes, int n_in,
                              void* d_out, int out_size) {
    const float* z_e = (const float*)d_in[0];
    const float* emb = (const float*)d_in[1];
    float* out = (float*)d_out;

    float* zq_out = out;
    float* loss_p = nullptr;
    float* perp_p = nullptr;
    float* idx_p  = nullptr;
    const int ZQ = NB * DDIM * HW;   // 4194304
    if (out_size >= ZQ + 2 + NROWS) {
        loss_p = out + ZQ;
        perp_p = out + ZQ + 1;
        idx_p  = out + ZQ + 2;
    }

    cudaFuncSetAttribute(vq_main_kernel,
                         cudaFuncAttributeMaxDynamicSharedMemorySize, SMEM_TOTAL);

    vq_prep_kernel<<<KNUM, 32>>>(emb);
    vq_main_kernel<<<NTILES, THREADS, SMEM_TOTAL>>>(z_e, emb, zq_out, idx_p);
    vq_finalize_kernel<<<1, KNUM>>>(loss_p, perp_p);
}